// round 7
// baseline (speedup 1.0000x reference)
#include <cuda_runtime.h>
#include <cstdint>

// PrototypeLoss: loss = 1 - (1/B) * sum_c || sum_{i: label_i=c} normalize(f_i) ||
// B = 262144, D = 256, C = 1000 (fixed shapes)
//
// ONE persistent co-resident kernel (grid = 592 = 148 SMs x 4 blocks,
// __launch_bounds__(256,4) guarantees co-residency):
//   phase 1: cooperative bucket scatter of row indices by label
//   device barrier (arrive counter + release flag; ticket reset in the window)
//   phase 2: work-stealing over 4000 (class,segment) units; each unit gathers
//            its rows (coalesced 1KB each), normalizes via warp reduction,
//            RED.ADDs a partial class sum; per-class ticket elects the norm
//            finisher; global ticket elects the output writer.
// All device state self-resets => graph-replayable with a single node.

static constexpr int C_CLS  = 1000;
static constexpr int D_DIM  = 256;
static constexpr int CAP    = 1024;        // bucket capacity (expected ~262)
static constexpr int NSEG   = 4;           // segments per class
static constexpr int SEGCAP = CAP / NSEG;  // 256
static constexpr int UNITS  = C_CLS * NSEG;
static constexpr int NBLK   = 592;         // 148 * 4, co-resident

__device__ int      g_cnt[C_CLS];          // reset by class finisher
__device__ int      g_idx[C_CLS * CAP];
__device__ float    g_sum[C_CLS * D_DIM];  // reset by class finisher
__device__ int      g_cdone[C_CLS];        // reset by class finisher
__device__ unsigned g_tick;                // reset by block 0 inside barrier
__device__ unsigned g_bar_arrive;          // reset by global finisher
__device__ unsigned g_bar_release;         // reset by global finisher
__device__ float    g_acc;                 // reset by global finisher
__device__ unsigned g_done;                // reset by global finisher

__global__ __launch_bounds__(256, 4) void proto_kernel(const float* __restrict__ f,
                                                       const void* __restrict__ labels,
                                                       float* __restrict__ out,
                                                       int B) {
    __shared__ int      s_idx[SEGCAP];
    __shared__ float    sm[8][8][33];      // [warp][slot][lane], padded
    __shared__ float    s_red[8];
    __shared__ int      s_is64;
    __shared__ unsigned s_unit;
    __shared__ int      s_fin;

    const int tid  = threadIdx.x;
    const int warp = tid >> 5;
    const int lane = tid & 31;

    // ---- label dtype probe (per block, reads first 1KB only) --------------
    // LE int64 labels in [0,1000) have every odd 32-bit word zero; 64 random
    // int32 labels all being zero has probability ~1e-192.
    const int* lbl32 = (const int*)labels;
    if (tid < 32) {
        int v = lbl32[2 * tid + 1] | lbl32[2 * tid + 65];
        unsigned any = __ballot_sync(0xffffffffu, v != 0);
        if (tid == 0) s_is64 = (any == 0u) ? 1 : 0;
    }
    __syncthreads();
    const int is64 = s_is64;

    // ---- phase 1: scatter -------------------------------------------------
    for (int i = blockIdx.x * 256 + tid; i < B; i += NBLK * 256) {
        int l = is64 ? (int)((const long long*)labels)[i] : lbl32[i];
        if ((unsigned)l < (unsigned)C_CLS) {
            int p = atomicAdd(&g_cnt[l], 1);
            if (p < CAP) g_idx[l * CAP + p] = i;
        }
    }

    // ---- device-wide barrier (all NBLK blocks co-resident) ----------------
    __syncthreads();
    __threadfence();
    if (tid == 0) {
        atomicAdd(&g_bar_arrive, 1u);
        if (blockIdx.x == 0) {
            while (atomicAdd(&g_bar_arrive, 0u) < (unsigned)NBLK) { }
            g_tick = 0u;                  // epoch-clean ticket reset
            __threadfence();
            atomicExch(&g_bar_release, 1u);
        } else {
            while (atomicAdd(&g_bar_release, 0u) == 0u) { }
        }
        __threadfence();
    }
    __syncthreads();

    // ---- phase 2: work-steal (class, segment) units -----------------------
    for (;;) {
        __syncthreads();                  // protects s_unit / s_idx reuse
        if (tid == 0) s_unit = atomicAdd(&g_tick, 1u);
        __syncthreads();
        unsigned u = s_unit;
        if (u >= (unsigned)UNITS) break;

        const int c   = (int)(u >> 2);    // NSEG == 4
        const int seg = (int)(u & 3u);
        int n = g_cnt[c];
        if (n > CAP) n = CAP;
        const int n_seg = (n > seg) ? ((n - seg + NSEG - 1) >> 2) : 0;

        // stage this segment's indices (entries e = seg + 4*t), coalesced
        const int* __restrict__ idx = &g_idx[c * CAP];
        for (int t = tid; t < n_seg; t += 256)
            s_idx[t] = idx[seg + (t << 2)];
        __syncthreads();

        float a0 = 0.f, a1 = 0.f, a2 = 0.f, a3 = 0.f;
        float a4 = 0.f, a5 = 0.f, a6 = 0.f, a7 = 0.f;

        int t = warp;
        for (; t + 8 < n_seg; t += 16) {  // 2-row unroll per warp
            int r0 = s_idx[t];
            int r1 = s_idx[t + 8];
            const float4* __restrict__ p0 = (const float4*)(f + (size_t)r0 * D_DIM);
            const float4* __restrict__ p1 = (const float4*)(f + (size_t)r1 * D_DIM);
            float4 x0 = p0[lane], y0 = p0[lane + 32];
            float4 x1 = p1[lane], y1 = p1[lane + 32];
            float s0 = x0.x*x0.x + x0.y*x0.y + x0.z*x0.z + x0.w*x0.w
                     + y0.x*y0.x + y0.y*y0.y + y0.z*y0.z + y0.w*y0.w;
            float s1 = x1.x*x1.x + x1.y*x1.y + x1.z*x1.z + x1.w*x1.w
                     + y1.x*y1.x + y1.y*y1.y + y1.z*y1.z + y1.w*y1.w;
            #pragma unroll
            for (int o = 16; o; o >>= 1) {
                s0 += __shfl_xor_sync(0xffffffffu, s0, o);
                s1 += __shfl_xor_sync(0xffffffffu, s1, o);
            }
            float i0 = rsqrtf(fmaxf(s0, 1e-24f));
            float i1 = rsqrtf(fmaxf(s1, 1e-24f));
            a0 += x0.x*i0 + x1.x*i1;  a1 += x0.y*i0 + x1.y*i1;
            a2 += x0.z*i0 + x1.z*i1;  a3 += x0.w*i0 + x1.w*i1;
            a4 += y0.x*i0 + y1.x*i1;  a5 += y0.y*i0 + y1.y*i1;
            a6 += y0.z*i0 + y1.z*i1;  a7 += y0.w*i0 + y1.w*i1;
        }
        if (t < n_seg) {
            int r = s_idx[t];
            const float4* __restrict__ p = (const float4*)(f + (size_t)r * D_DIM);
            float4 x = p[lane], y = p[lane + 32];
            float s = x.x*x.x + x.y*x.y + x.z*x.z + x.w*x.w
                    + y.x*y.x + y.y*y.y + y.z*y.z + y.w*y.w;
            #pragma unroll
            for (int o = 16; o; o >>= 1) s += __shfl_xor_sync(0xffffffffu, s, o);
            float iv = rsqrtf(fmaxf(s, 1e-24f));
            a0 += x.x*iv; a1 += x.y*iv; a2 += x.z*iv; a3 += x.w*iv;
            a4 += y.x*iv; a5 += y.y*iv; a6 += y.z*iv; a7 += y.w*iv;
        }

        // lane l slot k(0-3) -> element 4l+k ; slots 4-7 -> 128+4l+k
        sm[warp][0][lane] = a0; sm[warp][1][lane] = a1;
        sm[warp][2][lane] = a2; sm[warp][3][lane] = a3;
        sm[warp][4][lane] = a4; sm[warp][5][lane] = a5;
        sm[warp][6][lane] = a6; sm[warp][7][lane] = a7;
        __syncthreads();

        // thread e -> element e; combine 8 warps; one RED.ADD per element
        {
            int e    = tid;
            int lo   = (e < 128) ? e : (e - 128);
            int slot = ((e < 128) ? 0 : 4) + (lo & 3);
            int l    = lo >> 2;
            float v = 0.f;
            #pragma unroll
            for (int w = 0; w < 8; w++) v += sm[w][slot][l];
            atomicAdd(&g_sum[c * D_DIM + e], v);
        }

        __threadfence();
        __syncthreads();
        if (tid == 0) {
            int p = atomicAdd(&g_cdone[c], 1);
            s_fin = (p == NSEG - 1) ? 1 : 0;
        }
        __syncthreads();

        if (s_fin) {
            __threadfence();
            int e = tid;
            volatile float* gs = g_sum;
            float v = gs[c * D_DIM + e];
            g_sum[c * D_DIM + e] = 0.f;        // self-reset
            float ss = v * v;
            #pragma unroll
            for (int o = 16; o; o >>= 1) ss += __shfl_xor_sync(0xffffffffu, ss, o);
            if (lane == 0) s_red[warp] = ss;
            __syncthreads();
            if (tid == 0) {
                float tot = 0.f;
                #pragma unroll
                for (int w = 0; w < 8; w++) tot += s_red[w];
                atomicAdd(&g_acc, sqrtf(tot));
                g_cnt[c]   = 0;                // self-reset
                g_cdone[c] = 0;
                __threadfence();
                unsigned q = atomicAdd(&g_done, 1u);
                if (q == (unsigned)(C_CLS - 1)) {
                    __threadfence();
                    float acc = *((volatile float*)&g_acc);
                    out[0] = 1.0f - acc / (float)B;
                    g_acc         = 0.0f;      // global self-reset
                    g_done        = 0u;
                    g_bar_arrive  = 0u;
                    g_bar_release = 0u;
                }
            }
        }
    }
}

extern "C" void kernel_launch(void* const* d_in, const int* in_sizes, int n_in,
                              void* d_out, int out_size) {
    const float* features = (const float*)d_in[0];
    const void*  labels   = d_in[1];
    int B = in_sizes[1];                                    // 262144 labels
    if (B * D_DIM != in_sizes[0]) B = in_sizes[0] / D_DIM;  // defensive

    proto_kernel<<<NBLK, 256>>>(features, labels, (float*)d_out, B);
}

// round 8
// speedup vs baseline: 1.0446x; 1.0446x over previous
#include <cuda_runtime.h>
#include <cstdint>

// PrototypeLoss: loss = 1 - (1/B) * sum_c || sum_{i: label_i=c} normalize(f_i) ||
// B = 262144, D = 256, C = 1000 (fixed shapes)
//
// Two graph nodes:
//   scatter_kernel : bucket row indices by class (1 label/thread).
//   class_kernel   : one block per (class, segment). Rows are streamed
//                    GMEM->SMEM with cp.async.bulk + mbarrier double-buffering
//                    (thread 0 issues 16 x 1KB row copies per stage); 8 warps
//                    consume the previous stage from SMEM (conflict-free
//                    LDS.128), normalize per-row via warp reduction, and
//                    accumulate. Partial class sums merge via float RED.ADD;
//                    per-class ticket elects the norm finisher; global ticket
//                    elects the output writer. All state self-resets.

static constexpr int C_CLS  = 1000;
static constexpr int D_DIM  = 256;
static constexpr int CAP    = 1024;        // bucket capacity (expected ~262)
static constexpr int NSEG   = 2;           // segments per class
static constexpr int SEGCAP = CAP / NSEG;  // 512
static constexpr int SROWS  = 16;          // rows per pipeline stage (16KB)

__device__ int      g_cnt[C_CLS];          // reset by class finisher
__device__ int      g_idx[C_CLS * CAP];
__device__ float    g_sum[C_CLS * D_DIM];  // reset by class finisher
__device__ int      g_cdone[C_CLS];        // reset by class finisher
__device__ float    g_acc;                 // reset by global finisher
__device__ unsigned g_done;                // reset by global finisher

// ---------------- PTX helpers ----------------
__device__ __forceinline__ void mbar_init(unsigned a, unsigned cnt) {
    asm volatile("mbarrier.init.shared.b64 [%0], %1;" :: "r"(a), "r"(cnt) : "memory");
}
__device__ __forceinline__ void mbar_expect_tx(unsigned a, unsigned bytes) {
    asm volatile("mbarrier.arrive.expect_tx.shared.b64 _, [%0], %1;"
                 :: "r"(a), "r"(bytes) : "memory");
}
__device__ __forceinline__ void bulk_g2s(unsigned dst, const void* src,
                                         unsigned bytes, unsigned mbar) {
    asm volatile(
        "cp.async.bulk.shared::cluster.global.mbarrier::complete_tx::bytes "
        "[%0], [%1], %2, [%3];"
        :: "r"(dst), "l"(src), "r"(bytes), "r"(mbar) : "memory");
}
__device__ __forceinline__ void mbar_wait(unsigned a, unsigned ph) {
    asm volatile(
        "{\n\t.reg .pred P;\n\t"
        "W%=:\n\t"
        "mbarrier.try_wait.parity.acquire.cta.shared::cta.b64 P, [%0], %1, 0x989680;\n\t"
        "@P bra D%=;\n\t"
        "bra W%=;\n\t"
        "D%=:\n\t}"
        :: "r"(a), "r"(ph) : "memory");
}
__device__ __forceinline__ void fence_proxy_async_cta() {
    asm volatile("fence.proxy.async.shared::cta;" ::: "memory");
}

// ---------------------------------------------------------------------------
// Scatter: one label/thread. int64-vs-int32 probe: LE int64 labels in
// [0,1000) have all odd 32-bit words zero; 64 random int32 labels all being
// zero has probability ~1e-192. Probed words lie in the first 1KB.
// ---------------------------------------------------------------------------
__global__ __launch_bounds__(256) void scatter_kernel(const void* __restrict__ labels,
                                                      int B) {
    __shared__ int s_is64;
    const int* lbl32 = (const int*)labels;
    if (threadIdx.x < 32) {
        int v = lbl32[2 * threadIdx.x + 1] | lbl32[2 * threadIdx.x + 65];
        unsigned any = __ballot_sync(0xffffffffu, v != 0);
        if (threadIdx.x == 0) s_is64 = (any == 0u) ? 1 : 0;
    }
    __syncthreads();

    int i = blockIdx.x * 256 + threadIdx.x;
    if (i >= B) return;
    int l = s_is64 ? (int)((const long long*)labels)[i] : lbl32[i];
    if ((unsigned)l >= (unsigned)C_CLS) return;   // defensive
    int p = atomicAdd(&g_cnt[l], 1);
    if (p < CAP) g_idx[l * CAP + p] = i;
}

// ---------------------------------------------------------------------------
// class_kernel: block b -> class c = b/2, segment seg = b&1.
// Entries e = seg + 2*t. Pipeline: double-buffered 16-row stages via
// cp.async.bulk; warp w consumes staged rows 2w, 2w+1 per stage.
// ---------------------------------------------------------------------------
__global__ __launch_bounds__(256) void class_kernel(const float* __restrict__ f,
                                                    float* __restrict__ out,
                                                    int B) {
    __shared__ int   s_idx[SEGCAP];
    __shared__ __align__(16) float s_buf[2][SROWS][D_DIM];   // 32 KB
    __shared__ float sm[8][8][33];
    __shared__ float s_red[8];
    __shared__ int   s_fin;
    __shared__ __align__(8) unsigned long long s_mbar[2];

    const int tid  = threadIdx.x;
    const int warp = tid >> 5;
    const int lane = tid & 31;
    const int b    = blockIdx.x;
    const int c    = b >> 1;
    const int seg  = b & 1;

    int n = g_cnt[c];
    if (n > CAP) n = CAP;
    const int n_seg = (n > seg) ? ((n - seg + 1) >> 1) : 0;
    const int nstage = (n_seg + SROWS - 1) / SROWS;

    const int* __restrict__ idx = &g_idx[c * CAP];
    for (int t = tid; t < n_seg; t += 256)
        s_idx[t] = idx[seg + (t << 1)];

    const unsigned mb0 = (unsigned)__cvta_generic_to_shared(&s_mbar[0]);
    const unsigned mb1 = (unsigned)__cvta_generic_to_shared(&s_mbar[1]);
    if (tid == 0) {
        mbar_init(mb0, 1);
        mbar_init(mb1, 1);
        fence_proxy_async_cta();
    }
    __syncthreads();

    // prologue: issue stage 0
    if (tid == 0 && nstage > 0) {
        int rows0 = (n_seg < SROWS) ? n_seg : SROWS;
        mbar_expect_tx(mb0, (unsigned)rows0 * D_DIM * 4u);
        for (int k = 0; k < rows0; k++) {
            unsigned dst = (unsigned)__cvta_generic_to_shared(&s_buf[0][k][0]);
            bulk_g2s(dst, f + (size_t)s_idx[k] * D_DIM, D_DIM * 4u, mb0);
        }
    }

    float a0 = 0.f, a1 = 0.f, a2 = 0.f, a3 = 0.f;
    float a4 = 0.f, a5 = 0.f, a6 = 0.f, a7 = 0.f;
    unsigned p0 = 0, p1 = 0;

    for (int s = 0; s < nstage; s++) {
        const int bsel = s & 1;
        // issue next stage into the other buffer (consumed two stages ago)
        if (tid == 0 && s + 1 < nstage) {
            int base = (s + 1) * SROWS;
            int rowsn = n_seg - base; if (rowsn > SROWS) rowsn = SROWS;
            unsigned mbn = (bsel ? mb0 : mb1);
            mbar_expect_tx(mbn, (unsigned)rowsn * D_DIM * 4u);
            for (int k = 0; k < rowsn; k++) {
                unsigned dst = (unsigned)__cvta_generic_to_shared(&s_buf[bsel ^ 1][k][0]);
                bulk_g2s(dst, f + (size_t)s_idx[base + k] * D_DIM, D_DIM * 4u, mbn);
            }
        }
        // wait for this stage's data
        mbar_wait(bsel ? mb1 : mb0, bsel ? p1 : p0);
        if (bsel) p1 ^= 1u; else p0 ^= 1u;

        int rows = n_seg - s * SROWS; if (rows > SROWS) rows = SROWS;
        int r0 = warp << 1;
        int r1 = r0 + 1;
        if (r1 < rows) {
            const float4* __restrict__ q0 = (const float4*)&s_buf[bsel][r0][0];
            const float4* __restrict__ q1 = (const float4*)&s_buf[bsel][r1][0];
            float4 x0 = q0[lane], y0 = q0[lane + 32];
            float4 x1 = q1[lane], y1 = q1[lane + 32];
            float s0 = x0.x*x0.x + x0.y*x0.y + x0.z*x0.z + x0.w*x0.w
                     + y0.x*y0.x + y0.y*y0.y + y0.z*y0.z + y0.w*y0.w;
            float s1 = x1.x*x1.x + x1.y*x1.y + x1.z*x1.z + x1.w*x1.w
                     + y1.x*y1.x + y1.y*y1.y + y1.z*y1.z + y1.w*y1.w;
            #pragma unroll
            for (int o = 16; o; o >>= 1) {
                s0 += __shfl_xor_sync(0xffffffffu, s0, o);
                s1 += __shfl_xor_sync(0xffffffffu, s1, o);
            }
            float i0 = rsqrtf(fmaxf(s0, 1e-24f));
            float i1 = rsqrtf(fmaxf(s1, 1e-24f));
            a0 += x0.x*i0 + x1.x*i1;  a1 += x0.y*i0 + x1.y*i1;
            a2 += x0.z*i0 + x1.z*i1;  a3 += x0.w*i0 + x1.w*i1;
            a4 += y0.x*i0 + y1.x*i1;  a5 += y0.y*i0 + y1.y*i1;
            a6 += y0.z*i0 + y1.z*i1;  a7 += y0.w*i0 + y1.w*i1;
        } else if (r0 < rows) {
            const float4* __restrict__ q = (const float4*)&s_buf[bsel][r0][0];
            float4 x = q[lane], y = q[lane + 32];
            float sq = x.x*x.x + x.y*x.y + x.z*x.z + x.w*x.w
                     + y.x*y.x + y.y*y.y + y.z*y.z + y.w*y.w;
            #pragma unroll
            for (int o = 16; o; o >>= 1) sq += __shfl_xor_sync(0xffffffffu, sq, o);
            float iv = rsqrtf(fmaxf(sq, 1e-24f));
            a0 += x.x*iv; a1 += x.y*iv; a2 += x.z*iv; a3 += x.w*iv;
            a4 += y.x*iv; a5 += y.y*iv; a6 += y.z*iv; a7 += y.w*iv;
        }
        __syncthreads();   // all consumers done before buffer reissue
    }

    // lane l slot k(0-3) -> element 4l+k ; slots 4-7 -> 128+4l+k
    sm[warp][0][lane] = a0; sm[warp][1][lane] = a1;
    sm[warp][2][lane] = a2; sm[warp][3][lane] = a3;
    sm[warp][4][lane] = a4; sm[warp][5][lane] = a5;
    sm[warp][6][lane] = a6; sm[warp][7][lane] = a7;
    __syncthreads();

    {   // thread e -> element e; combine 8 warps; one RED.ADD
        int e    = tid;
        int lo   = (e < 128) ? e : (e - 128);
        int slot = ((e < 128) ? 0 : 4) + (lo & 3);
        int l    = lo >> 2;
        float v = 0.f;
        #pragma unroll
        for (int w = 0; w < 8; w++) v += sm[w][slot][l];
        atomicAdd(&g_sum[c * D_DIM + e], v);
    }

    __threadfence();
    __syncthreads();
    if (tid == 0) {
        int p = atomicAdd(&g_cdone[c], 1);
        s_fin = (p == NSEG - 1) ? 1 : 0;
    }
    __syncthreads();

    if (s_fin) {
        __threadfence();
        int e = tid;
        volatile float* gs = g_sum;
        float v = gs[c * D_DIM + e];
        g_sum[c * D_DIM + e] = 0.f;            // self-reset
        float ss = v * v;
        #pragma unroll
        for (int o = 16; o; o >>= 1) ss += __shfl_xor_sync(0xffffffffu, ss, o);
        if (lane == 0) s_red[warp] = ss;
        __syncthreads();
        if (tid == 0) {
            float tot = 0.f;
            #pragma unroll
            for (int w = 0; w < 8; w++) tot += s_red[w];
            atomicAdd(&g_acc, sqrtf(tot));
            g_cnt[c]   = 0;                    // self-reset
            g_cdone[c] = 0;
            __threadfence();
            unsigned q = atomicAdd(&g_done, 1u);
            if (q == (unsigned)(C_CLS - 1)) {
                __threadfence();
                float acc = *((volatile float*)&g_acc);
                out[0] = 1.0f - acc / (float)B;
                g_acc  = 0.0f;                 // global self-reset
                g_done = 0u;
            }
        }
    }
}

extern "C" void kernel_launch(void* const* d_in, const int* in_sizes, int n_in,
                              void* d_out, int out_size) {
    const float* features = (const float*)d_in[0];
    const void*  labels   = d_in[1];
    int B = in_sizes[1];                                    // 262144 labels
    if (B * D_DIM != in_sizes[0]) B = in_sizes[0] / D_DIM;  // defensive

    scatter_kernel<<<(B + 255) / 256, 256>>>(labels, B);
    class_kernel<<<C_CLS * NSEG, 256>>>(features, (float*)d_out, B);
}

// round 9
// speedup vs baseline: 1.3825x; 1.3235x over previous
#include <cuda_runtime.h>
#include <cstdint>

// PrototypeLoss: loss = 1 - (1/B) * sum_c || sum_{i: label_i=c} normalize(f_i) ||
// B = 262144, D = 256, C = 1000 (fixed shapes)
//
// Two graph nodes:
//   scatter_kernel : bucket row indices by class. Counters are padded to one
//                    per 128B cache line so the 262K ATOMGs spread across all
//                    ~184 LTS partitions instead of serializing on 32 lines.
//   class_kernel   : NSEG=8 segment blocks per class (grid 8000, 128 thr);
//                    each warp gathers rows (coalesced 1KB), normalizes via
//                    warp shuffle reduction (2-row unroll), accumulates;
//                    partial class sums merge via float RED.ADD; per-class
//                    ticket elects the norm finisher; global ticket elects the
//                    output writer. All state self-resets (graph-replayable;
//                    __device__ globals are zeroed at module load).

static constexpr int C_CLS   = 1000;
static constexpr int D_DIM   = 256;
static constexpr int CAP     = 1024;   // bucket capacity (expected ~262/class)
static constexpr int NSEG    = 8;      // segment blocks per class
static constexpr int CNT_PAD = 32;     // ints per counter line (128B)

__device__ int      g_cnt[C_CLS * CNT_PAD];  // padded; reset by finisher
__device__ int      g_idx[C_CLS * CAP];
__device__ float    g_sum[C_CLS * D_DIM];    // reset by finisher
__device__ int      g_cdone[C_CLS];          // reset by finisher
__device__ float    g_acc;                   // reset by global finisher
__device__ unsigned g_done;                  // reset by global finisher

// ---------------------------------------------------------------------------
// Scatter: one label per thread, one padded-line atomic per thread.
// int64-vs-int32 probe: LE int64 labels in [0,1000) have all odd 32-bit words
// zero; 64 random int32 labels all being zero has probability ~1e-192.
// Probed words lie in the first 1KB (valid under either dtype).
// ---------------------------------------------------------------------------
__global__ __launch_bounds__(512) void scatter_kernel(const void* __restrict__ labels,
                                                      int B) {
    __shared__ int s_is64;
    const int* lbl32 = (const int*)labels;
    if (threadIdx.x < 32) {
        int v = lbl32[2 * threadIdx.x + 1] | lbl32[2 * threadIdx.x + 65];
        unsigned any = __ballot_sync(0xffffffffu, v != 0);
        if (threadIdx.x == 0) s_is64 = (any == 0u) ? 1 : 0;
    }
    __syncthreads();

    int i = blockIdx.x * 512 + threadIdx.x;
    if (i >= B) return;
    int l = s_is64 ? (int)((const long long*)labels)[i] : lbl32[i];
    if ((unsigned)l >= (unsigned)C_CLS) return;   // defensive
    int p = atomicAdd(&g_cnt[l * CNT_PAD], 1);
    if (p < CAP) g_idx[l * CAP + p] = i;
}

// ---------------------------------------------------------------------------
// class_kernel: block b -> class c = b/NSEG, segment s = b%NSEG.
// Segment s processes bucket entries e = s + NSEG*j; warp w (of 4) takes
// j = w mod 4. Each row: 2x float4 per lane (coalesced 1KB), warp-shuffle
// sumsq, rsqrt, accumulate 8 regs/lane. 2-row unroll. No block barrier in
// the hot loop.
// ---------------------------------------------------------------------------
__global__ __launch_bounds__(128) void class_kernel(const float* __restrict__ f,
                                                    float* __restrict__ out,
                                                    int B) {
    __shared__ float sm[4][8][33];   // [warp][slot][lane], padded
    __shared__ int   s_fin;
    const int b    = blockIdx.x;
    const int c    = b >> 3;         // NSEG == 8
    const int seg  = b & 7;
    int n = g_cnt[c * CNT_PAD];
    if (n > CAP) n = CAP;
    const int warp = threadIdx.x >> 5;
    const int lane = threadIdx.x & 31;

    float a0 = 0.f, a1 = 0.f, a2 = 0.f, a3 = 0.f;
    float a4 = 0.f, a5 = 0.f, a6 = 0.f, a7 = 0.f;
    const int* __restrict__ idx = &g_idx[c * CAP];

    int j = warp;
    for (; seg + ((j + 4) << 3) < n; j += 8) {
        int row0 = idx[seg + (j << 3)];
        int row1 = idx[seg + ((j + 4) << 3)];
        const float4* __restrict__ p0 = (const float4*)(f + (size_t)row0 * D_DIM);
        const float4* __restrict__ p1 = (const float4*)(f + (size_t)row1 * D_DIM);
        float4 x0 = p0[lane], y0 = p0[lane + 32];
        float4 x1 = p1[lane], y1 = p1[lane + 32];
        float s0 = x0.x*x0.x + x0.y*x0.y + x0.z*x0.z + x0.w*x0.w
                 + y0.x*y0.x + y0.y*y0.y + y0.z*y0.z + y0.w*y0.w;
        float s1 = x1.x*x1.x + x1.y*x1.y + x1.z*x1.z + x1.w*x1.w
                 + y1.x*y1.x + y1.y*y1.y + y1.z*y1.z + y1.w*y1.w;
        #pragma unroll
        for (int o = 16; o; o >>= 1) {
            s0 += __shfl_xor_sync(0xffffffffu, s0, o);
            s1 += __shfl_xor_sync(0xffffffffu, s1, o);
        }
        float i0 = rsqrtf(fmaxf(s0, 1e-24f));
        float i1 = rsqrtf(fmaxf(s1, 1e-24f));
        a0 += x0.x*i0 + x1.x*i1;  a1 += x0.y*i0 + x1.y*i1;
        a2 += x0.z*i0 + x1.z*i1;  a3 += x0.w*i0 + x1.w*i1;
        a4 += y0.x*i0 + y1.x*i1;  a5 += y0.y*i0 + y1.y*i1;
        a6 += y0.z*i0 + y1.z*i1;  a7 += y0.w*i0 + y1.w*i1;
    }
    for (; seg + (j << 3) < n; j += 4) {
        int row = idx[seg + (j << 3)];
        const float4* __restrict__ p = (const float4*)(f + (size_t)row * D_DIM);
        float4 x = p[lane], y = p[lane + 32];
        float s = x.x*x.x + x.y*x.y + x.z*x.z + x.w*x.w
                + y.x*y.x + y.y*y.y + y.z*y.z + y.w*y.w;
        #pragma unroll
        for (int o = 16; o; o >>= 1) s += __shfl_xor_sync(0xffffffffu, s, o);
        float iv = rsqrtf(fmaxf(s, 1e-24f));
        a0 += x.x*iv; a1 += x.y*iv; a2 += x.z*iv; a3 += x.w*iv;
        a4 += y.x*iv; a5 += y.y*iv; a6 += y.z*iv; a7 += y.w*iv;
    }

    // lane l slot k(0-3) -> element 4l+k ; slots 4-7 -> 128+4l+k
    sm[warp][0][lane] = a0; sm[warp][1][lane] = a1;
    sm[warp][2][lane] = a2; sm[warp][3][lane] = a3;
    sm[warp][4][lane] = a4; sm[warp][5][lane] = a5;
    sm[warp][6][lane] = a6; sm[warp][7][lane] = a7;
    __syncthreads();

    // thread t -> elements t and t+128; combine 4 warps; RED.ADD into g_sum
    {
        int t  = threadIdx.x;                 // 0..127
        int l0 = t >> 2, k0 = t & 3;
        float v0 = sm[0][k0][l0] + sm[1][k0][l0] + sm[2][k0][l0] + sm[3][k0][l0];
        float v1 = sm[0][4 + k0][l0] + sm[1][4 + k0][l0]
                 + sm[2][4 + k0][l0] + sm[3][4 + k0][l0];
        atomicAdd(&g_sum[c * D_DIM + t], v0);
        atomicAdd(&g_sum[c * D_DIM + t + 128], v1);
    }

    __threadfence();
    __syncthreads();
    if (threadIdx.x == 0) {
        int p = atomicAdd(&g_cdone[c], 1);
        s_fin = (p == NSEG - 1) ? 1 : 0;
    }
    __syncthreads();

    if (s_fin) {
        __threadfence();
        int t = threadIdx.x;
        volatile float* gs = g_sum;
        float v0 = gs[c * D_DIM + t];
        float v1 = gs[c * D_DIM + t + 128];
        g_sum[c * D_DIM + t] = 0.f;            // self-reset
        g_sum[c * D_DIM + t + 128] = 0.f;
        float ss = v0 * v0 + v1 * v1;
        #pragma unroll
        for (int o = 16; o; o >>= 1) ss += __shfl_xor_sync(0xffffffffu, ss, o);
        if (lane == 0) sm[0][0][warp] = ss;
        __syncthreads();
        if (threadIdx.x == 0) {
            float tot = sm[0][0][0] + sm[0][0][1] + sm[0][0][2] + sm[0][0][3];
            atomicAdd(&g_acc, sqrtf(tot));
            g_cnt[c * CNT_PAD] = 0;            // self-reset
            g_cdone[c]         = 0;
            __threadfence();
            unsigned q = atomicAdd(&g_done, 1u);
            if (q == (unsigned)(C_CLS - 1)) {
                __threadfence();
                float acc = *((volatile float*)&g_acc);
                out[0] = 1.0f - acc / (float)B;
                g_acc  = 0.0f;                 // global self-reset
                g_done = 0u;
            }
        }
    }
}

extern "C" void kernel_launch(void* const* d_in, const int* in_sizes, int n_in,
                              void* d_out, int out_size) {
    const float* features = (const float*)d_in[0];
    const void*  labels   = d_in[1];
    int B = in_sizes[1];                                    // 262144 labels
    if (B * D_DIM != in_sizes[0]) B = in_sizes[0] / D_DIM;  // defensive

    scatter_kernel<<<(B + 511) / 512, 512>>>(labels, B);
    class_kernel<<<C_CLS * NSEG, 128>>>(features, (float*)d_out, B);
}